// round 4
// baseline (speedup 1.0000x reference)
#include <cuda_runtime.h>
#include <math.h>

// Problem shapes (fixed by the dataset)
#define BATCH 2
#define SEQ   4096
#define HID   2048
#define SOFTMAX_SCALE 0.08838834764831843f  /* 1/sqrt(128) */

#define BM 128
#define BN 128
#define BK 16

// Scratch (allocation-free rule: __device__ globals)
__device__ float g_q[(long long)BATCH * SEQ * HID];
__device__ float g_k[(long long)BATCH * SEQ * HID];
__device__ float g_v[(long long)BATCH * SEQ * HID];
__device__ float g_s[(long long)BATCH * SEQ * SEQ];

// C = alpha * A @ op(B) (+ bias), row-major everywhere.
// TRANS_B: B is [N,K] row-major (NT gemm).  !TRANS_B: B is [K,N] row-major (NN gemm).
template<bool TRANS_B, bool ADD_BIAS>
__global__ __launch_bounds__(256)
void gemm_kernel(const float* __restrict__ A, const float* __restrict__ B,
                 const float* __restrict__ bias, float* __restrict__ C,
                 int M, int N, int K, float alpha,
                 long long sA, long long sB, long long sC)
{
    __shared__ float As[BK][BM];
    __shared__ float Bs[BK][BN];

    const float* Ab = A + (long long)blockIdx.z * sA;
    const float* Bp = B + (long long)blockIdx.z * sB;
    float*       Cb = C + (long long)blockIdx.z * sC;

    const int tid  = threadIdx.x;
    const int tx   = tid & 15;   // 0..15, N direction
    const int ty   = tid >> 4;   // 0..15, M direction
    const int row0 = blockIdx.y * BM;
    const int col0 = blockIdx.x * BN;

    float acc[8][8];
#pragma unroll
    for (int i = 0; i < 8; ++i)
#pragma unroll
        for (int j = 0; j < 8; ++j) acc[i][j] = 0.f;

    for (int k0 = 0; k0 < K; k0 += BK) {
        // ---- A tile: [BM x BK], stored transposed As[k][m]. float4 along K.
#pragma unroll
        for (int p = 0; p < 2; ++p) {
            int idx = tid + p * 256;          // float4 index 0..511
            int m   = idx >> 2;               // 0..127
            int c   = (idx & 3) * 4;          // 0,4,8,12
            float4 v = *reinterpret_cast<const float4*>(
                &Ab[(long long)(row0 + m) * K + k0 + c]);
            As[c + 0][m] = v.x; As[c + 1][m] = v.y;
            As[c + 2][m] = v.z; As[c + 3][m] = v.w;
        }
        // ---- B tile
        if (TRANS_B) {
#pragma unroll
            for (int p = 0; p < 2; ++p) {
                int idx = tid + p * 256;
                int n   = idx >> 2;
                int c   = (idx & 3) * 4;
                float4 v = *reinterpret_cast<const float4*>(
                    &Bp[(long long)(col0 + n) * K + k0 + c]);
                Bs[c + 0][n] = v.x; Bs[c + 1][n] = v.y;
                Bs[c + 2][n] = v.z; Bs[c + 3][n] = v.w;
            }
        } else {
#pragma unroll
            for (int p = 0; p < 2; ++p) {
                int idx = tid + p * 256;
                int kk  = idx >> 5;           // 0..15
                int n4  = idx & 31;           // float4 column
                float4 v = *reinterpret_cast<const float4*>(
                    &Bp[(long long)(k0 + kk) * N + col0 + n4 * 4]);
                *reinterpret_cast<float4*>(&Bs[kk][n4 * 4]) = v;
            }
        }
        __syncthreads();

#pragma unroll
        for (int kk = 0; kk < BK; ++kk) {
            float4 a0 = *reinterpret_cast<const float4*>(&As[kk][ty * 8]);
            float4 a1 = *reinterpret_cast<const float4*>(&As[kk][ty * 8 + 4]);
            float4 b0 = *reinterpret_cast<const float4*>(&Bs[kk][tx * 8]);
            float4 b1 = *reinterpret_cast<const float4*>(&Bs[kk][tx * 8 + 4]);
            float a[8] = {a0.x, a0.y, a0.z, a0.w, a1.x, a1.y, a1.z, a1.w};
            float b[8] = {b0.x, b0.y, b0.z, b0.w, b1.x, b1.y, b1.z, b1.w};
#pragma unroll
            for (int i = 0; i < 8; ++i)
#pragma unroll
                for (int j = 0; j < 8; ++j)
                    acc[i][j] = fmaf(a[i], b[j], acc[i][j]);
        }
        __syncthreads();
    }

    // ---- epilogue
    float bval[8];
#pragma unroll
    for (int j = 0; j < 8; ++j)
        bval[j] = ADD_BIAS ? bias[col0 + tx * 8 + j] : 0.f;

#pragma unroll
    for (int i = 0; i < 8; ++i) {
        long long m = row0 + ty * 8 + i;
        int n = col0 + tx * 8;
        float4 o0, o1;
        o0.x = fmaf(acc[i][0], alpha, bval[0]);
        o0.y = fmaf(acc[i][1], alpha, bval[1]);
        o0.z = fmaf(acc[i][2], alpha, bval[2]);
        o0.w = fmaf(acc[i][3], alpha, bval[3]);
        o1.x = fmaf(acc[i][4], alpha, bval[4]);
        o1.y = fmaf(acc[i][5], alpha, bval[5]);
        o1.z = fmaf(acc[i][6], alpha, bval[6]);
        o1.w = fmaf(acc[i][7], alpha, bval[7]);
        *reinterpret_cast<float4*>(&Cb[m * N + n])     = o0;
        *reinterpret_cast<float4*>(&Cb[m * N + n + 4]) = o1;
    }
}

// Row softmax over g_s (in place), with additive mask[b, 0, k] broadcast over rows.
// One block per row; 256 threads * 16 elems = 4096 columns held in registers.
__global__ __launch_bounds__(256)
void softmax_kernel(float* __restrict__ S, const float* __restrict__ mask)
{
    const int row = blockIdx.x;            // 0 .. BATCH*SEQ-1
    const int b   = row / SEQ;
    float* srow = S + (long long)row * SEQ;
    const float* mrow = mask + (long long)b * SEQ;
    const int t = threadIdx.x;

    float v[16];
    float mx = -INFINITY;
#pragma unroll
    for (int i = 0; i < 16; ++i) {
        int c = t + i * 256;
        v[i] = srow[c] + mrow[c];
        mx = fmaxf(mx, v[i]);
    }

    __shared__ float red[256];
    red[t] = mx; __syncthreads();
#pragma unroll
    for (int s = 128; s > 0; s >>= 1) {
        if (t < s) red[t] = fmaxf(red[t], red[t + s]);
        __syncthreads();
    }
    mx = red[0];
    __syncthreads();

    float sum = 0.f;
#pragma unroll
    for (int i = 0; i < 16; ++i) {
        v[i] = __expf(v[i] - mx);
        sum += v[i];
    }
    red[t] = sum; __syncthreads();
#pragma unroll
    for (int s = 128; s > 0; s >>= 1) {
        if (t < s) red[t] += red[t + s];
        __syncthreads();
    }
    const float inv = 1.f / red[0];

#pragma unroll
    for (int i = 0; i < 16; ++i)
        srow[t + i * 256] = v[i] * inv;
}

extern "C" void kernel_launch(void* const* d_in, const int* in_sizes, int n_in,
                              void* d_out, int out_size)
{
    const float* hs   = (const float*)d_in[0];  // [B,S,H]
    const float* mask = (const float*)d_in[1];  // [B,1,S]
    const float* Wq   = (const float*)d_in[2];  // [H,H]
    const float* bq   = (const float*)d_in[3];
    const float* Wk   = (const float*)d_in[4];
    const float* bk   = (const float*)d_in[5];
    const float* Wv   = (const float*)d_in[6];
    const float* bv   = (const float*)d_in[7];
    float* out = (float*)d_out;

    float *p_q, *p_k, *p_v, *p_s;
    cudaGetSymbolAddress((void**)&p_q, g_q);
    cudaGetSymbolAddress((void**)&p_k, g_k);
    cudaGetSymbolAddress((void**)&p_v, g_v);
    cudaGetSymbolAddress((void**)&p_s, g_s);

    const int MS = BATCH * SEQ;                 // 8192 rows for QKV projections
    dim3 blk(256);

    // Q/K/V projections: [8192,2048] @ W[2048,2048]^T + bias  (NT)
    dim3 gqkv(HID / BN, MS / BM, 1);
    gemm_kernel<true, true><<<gqkv, blk>>>(hs, Wq, bq, p_q, MS, HID, HID, 1.f, 0, 0, 0);
    gemm_kernel<true, true><<<gqkv, blk>>>(hs, Wk, bk, p_k, MS, HID, HID, 1.f, 0, 0, 0);
    gemm_kernel<true, true><<<gqkv, blk>>>(hs, Wv, bv, p_v, MS, HID, HID, 1.f, 0, 0, 0);

    // scores[b] = (Q[b] @ K[b]^T) / sqrt(128)   (NT, batched via blockIdx.z)
    dim3 gsc(SEQ / BN, SEQ / BM, BATCH);
    gemm_kernel<true, false><<<gsc, blk>>>(p_q, p_k, nullptr, p_s,
                                           SEQ, SEQ, HID, SOFTMAX_SCALE,
                                           (long long)SEQ * HID,
                                           (long long)SEQ * HID,
                                           (long long)SEQ * SEQ);

    // softmax(scores + mask) in place
    softmax_kernel<<<BATCH * SEQ, 256>>>(p_s, mask);

    // context[b] = P[b] @ V[b]   (NN, batched)
    dim3 gct(HID / BN, SEQ / BM, BATCH);
    gemm_kernel<false, false><<<gct, blk>>>(p_s, p_v, nullptr, out,
                                            SEQ, HID, SEQ, 1.f,
                                            (long long)SEQ * SEQ,
                                            (long long)SEQ * HID,
                                            (long long)SEQ * HID);
}

// round 7
// speedup vs baseline: 1.7579x; 1.7579x over previous
#include <cuda_runtime.h>
#include <math.h>
#include <stdint.h>

// Problem shapes (fixed by the dataset)
#define BATCH 2
#define SEQ   4096
#define HID   2048
#define SOFTMAX_SCALE 0.08838834764831843f  /* 1/sqrt(128) */

#define BM 128
#define BN 128
#define BK 16

#define SMEM_TF32 65536  /* 2 stages * (A 16KB + B 16KB) */

// ---------------- scratch (__device__ globals: allocation-free rule) ---------
__device__ float g_q [(long long)BATCH * SEQ * HID];   // tf32(Q)
__device__ float g_k [(long long)BATCH * SEQ * HID];   // tf32(K)
__device__ float g_vt[(long long)BATCH * HID * SEQ];   // tf32(V^T) [b][h][s]
__device__ float g_s [(long long)BATCH * SEQ * SEQ];   // scores / probs

// ---------------- PTX helpers ------------------------------------------------
__device__ __forceinline__ float f2tf32(float x) {
    uint32_t u;
    asm("cvt.rna.tf32.f32 %0, %1;" : "=r"(u) : "f"(x));
    return __uint_as_float(u);
}

__device__ __forceinline__ void ldsm4(uint32_t* r, uint32_t addr) {
    asm volatile("ldmatrix.sync.aligned.m8n8.x4.shared.b16 {%0,%1,%2,%3}, [%4];\n"
                 : "=r"(r[0]), "=r"(r[1]), "=r"(r[2]), "=r"(r[3]) : "r"(addr));
}

__device__ __forceinline__ void mma_tf32(float* d, const uint32_t* a, const uint32_t* b) {
    asm volatile(
        "mma.sync.aligned.m16n8k8.row.col.f32.tf32.tf32.f32 "
        "{%0,%1,%2,%3}, {%4,%5,%6,%7}, {%8,%9}, {%0,%1,%2,%3};\n"
        : "+f"(d[0]), "+f"(d[1]), "+f"(d[2]), "+f"(d[3])
        : "r"(a[0]), "r"(a[1]), "r"(a[2]), "r"(a[3]), "r"(b[0]), "r"(b[1]));
}

__device__ __forceinline__ void cp_async16(uint32_t dst, const void* src) {
    asm volatile("cp.async.cg.shared.global [%0], [%1], 16;\n" :: "r"(dst), "l"(src));
}
__device__ __forceinline__ void cp_commit() { asm volatile("cp.async.commit_group;\n"); }
__device__ __forceinline__ void cp_wait1()  { asm volatile("cp.async.wait_group 1;\n"); }
__device__ __forceinline__ void cp_wait0()  { asm volatile("cp.async.wait_group 0;\n"); }

// ============================================================================
// fp32 NT GEMM (R4-proven path) for the QKV projections.
// C = A[M,K] @ B[N,K]^T + bias.  Output tf32-rounded; V optionally transposed.
// ============================================================================
template<bool STORE_TRANS>
__global__ __launch_bounds__(256)
void gemm_f32_qkv(const float* __restrict__ A, const float* __restrict__ B,
                  const float* __restrict__ bias, float* __restrict__ C,
                  int M, int N, int K)
{
    __shared__ float As[BK][BM];
    __shared__ float Bs[BK][BN];

    const int tid  = threadIdx.x;
    const int tx   = tid & 15;
    const int ty   = tid >> 4;
    const int row0 = blockIdx.y * BM;
    const int col0 = blockIdx.x * BN;

    float acc[8][8];
#pragma unroll
    for (int i = 0; i < 8; ++i)
#pragma unroll
        for (int j = 0; j < 8; ++j) acc[i][j] = 0.f;

    for (int k0 = 0; k0 < K; k0 += BK) {
#pragma unroll
        for (int p = 0; p < 2; ++p) {
            int idx = tid + p * 256;
            int m   = idx >> 2;
            int c   = (idx & 3) * 4;
            float4 v = *reinterpret_cast<const float4*>(
                &A[(long long)(row0 + m) * K + k0 + c]);
            As[c + 0][m] = v.x; As[c + 1][m] = v.y;
            As[c + 2][m] = v.z; As[c + 3][m] = v.w;
        }
#pragma unroll
        for (int p = 0; p < 2; ++p) {
            int idx = tid + p * 256;
            int n   = idx >> 2;
            int c   = (idx & 3) * 4;
            float4 v = *reinterpret_cast<const float4*>(
                &B[(long long)(col0 + n) * K + k0 + c]);
            Bs[c + 0][n] = v.x; Bs[c + 1][n] = v.y;
            Bs[c + 2][n] = v.z; Bs[c + 3][n] = v.w;
        }
        __syncthreads();

#pragma unroll
        for (int kk = 0; kk < BK; ++kk) {
            float4 a0 = *reinterpret_cast<const float4*>(&As[kk][ty * 8]);
            float4 a1 = *reinterpret_cast<const float4*>(&As[kk][ty * 8 + 4]);
            float4 b0 = *reinterpret_cast<const float4*>(&Bs[kk][tx * 8]);
            float4 b1 = *reinterpret_cast<const float4*>(&Bs[kk][tx * 8 + 4]);
            float a[8] = {a0.x, a0.y, a0.z, a0.w, a1.x, a1.y, a1.z, a1.w};
            float b[8] = {b0.x, b0.y, b0.z, b0.w, b1.x, b1.y, b1.z, b1.w};
#pragma unroll
            for (int i = 0; i < 8; ++i)
#pragma unroll
                for (int j = 0; j < 8; ++j)
                    acc[i][j] = fmaf(a[i], b[j], acc[i][j]);
        }
        __syncthreads();
    }

    float bval[8];
#pragma unroll
    for (int j = 0; j < 8; ++j) bval[j] = bias[col0 + tx * 8 + j];

#pragma unroll
    for (int i = 0; i < 8; ++i) {
        const long long m = row0 + ty * 8 + i;
        const int n = col0 + tx * 8;
        float v[8];
#pragma unroll
        for (int j = 0; j < 8; ++j) v[j] = f2tf32(acc[i][j] + bval[j]);
        if (STORE_TRANS) {
            // out[b][h][s]: b = m/SEQ, s = m%SEQ, h = n+j
            const long long bb = m >> 12;
            const long long s  = m & 4095;
            float* Ct = C + bb * ((long long)HID * SEQ);
#pragma unroll
            for (int j = 0; j < 8; ++j) Ct[(long long)(n + j) * SEQ + s] = v[j];
        } else {
            float4 o0 = make_float4(v[0], v[1], v[2], v[3]);
            float4 o1 = make_float4(v[4], v[5], v[6], v[7]);
            *reinterpret_cast<float4*>(&C[m * N + n])     = o0;
            *reinterpret_cast<float4*>(&C[m * N + n + 4]) = o1;
        }
    }
}

// ============================================================================
// tf32 NT GEMM (tensor core) for scores and context.
// C[M,N] = alpha * A[M,K] @ B[N,K]^T; inputs already tf32-rounded f32.
// BM=BN=128, BK=32, 256 threads (8 warps 4x2), warp tile 32x64, m16n8k8,
// XOR-swizzled smem + cp.async 2-stage pipeline.
// ============================================================================
__global__ __launch_bounds__(256)
void gemm_tf32(const float* __restrict__ A, const float* __restrict__ B,
               float* __restrict__ C, int M, int N, int K, float alpha,
               long long sA, long long sB, long long sC)
{
    extern __shared__ float sm[];
    const int tid    = threadIdx.x;
    const int lane   = tid & 31;
    const int wid    = tid >> 5;
    const int warp_m = wid & 3;
    const int warp_n = wid >> 2;
    const long long row0 = (long long)blockIdx.y * 128;
    const long long col0 = (long long)blockIdx.x * 128;

    const float* Ab = A + (long long)blockIdx.z * sA;
    const float* Bb = B + (long long)blockIdx.z * sB;

    const uint32_t smem_base = (uint32_t)__cvta_generic_to_shared(sm);

    float acc[2][8][4];
#pragma unroll
    for (int t = 0; t < 2; ++t)
#pragma unroll
        for (int j = 0; j < 8; ++j)
#pragma unroll
            for (int r = 0; r < 4; ++r) acc[t][j][r] = 0.f;

    const int KT = K >> 5;

    auto stage = [&](int kt, int buf) {
        const long long k0 = (long long)kt * 32;
        const uint32_t abase = smem_base + buf * 32768u;
        const uint32_t bbase = abase + 16384u;
#pragma unroll
        for (int p = 0; p < 4; ++p) {
            int idx = p * 256 + tid;
            int m = idx >> 3;
            int c = idx & 7;
            uint32_t off = (uint32_t)(((m << 3) + (c ^ (m & 7))) << 4);
            cp_async16(abase + off, Ab + (row0 + m) * K + k0 + c * 4);
            cp_async16(bbase + off, Bb + (col0 + m) * K + k0 + c * 4);
        }
    };

    const int r15       = lane & 15;
    const int a_chunk_h = lane >> 4;
    const int b_row_off = (lane & 7) + ((lane >> 4) << 3);
    const int b_chunk_h = (lane >> 3) & 1;

    auto compute = [&](int buf) {
        const uint32_t abase = smem_base + buf * 32768u;
        const uint32_t bbase = abase + 16384u;
#pragma unroll
        for (int ks = 0; ks < 4; ++ks) {
            uint32_t a[2][4];
#pragma unroll
            for (int t = 0; t < 2; ++t) {
                int row   = warp_m * 32 + t * 16 + r15;
                int chunk = 2 * ks + a_chunk_h;
                ldsm4(a[t], abase + (uint32_t)(((row << 3) + (chunk ^ (row & 7))) << 4));
            }
            uint32_t b[8][2];
#pragma unroll
            for (int u = 0; u < 4; ++u) {
                int row   = warp_n * 64 + u * 16 + b_row_off;
                int chunk = 2 * ks + b_chunk_h;
                uint32_t r[4];
                ldsm4(r, bbase + (uint32_t)(((row << 3) + (chunk ^ (row & 7))) << 4));
                b[2*u  ][0] = r[0]; b[2*u  ][1] = r[1];
                b[2*u+1][0] = r[2]; b[2*u+1][1] = r[3];
            }
#pragma unroll
            for (int t = 0; t < 2; ++t)
#pragma unroll
                for (int j = 0; j < 8; ++j)
                    mma_tf32(acc[t][j], a[t], b[j]);
        }
    };

    stage(0, 0); cp_commit();
    for (int kt = 0; kt < KT; ++kt) {
        if (kt + 1 < KT) { stage(kt + 1, (kt + 1) & 1); cp_commit(); cp_wait1(); }
        else            { cp_wait0(); }
        __syncthreads();
        compute(kt & 1);
        __syncthreads();
    }

    float* Cb = C + (long long)blockIdx.z * sC;
    const int lrow = lane >> 2;
    const int lcol = (lane & 3) * 2;
#pragma unroll
    for (int t = 0; t < 2; ++t)
#pragma unroll
        for (int j = 0; j < 8; ++j) {
            const long long gcol = col0 + warp_n * 64 + j * 8 + lcol;
#pragma unroll
            for (int h = 0; h < 2; ++h) {
                const long long grow = row0 + warp_m * 32 + t * 16 + lrow + h * 8;
                float v0 = acc[t][j][h * 2 + 0] * alpha;
                float v1 = acc[t][j][h * 2 + 1] * alpha;
                *reinterpret_cast<float2*>(&Cb[grow * N + gcol]) = make_float2(v0, v1);
            }
        }
}

// ---------------- softmax (in place) + tf32-round output ---------------------
__global__ __launch_bounds__(256)
void softmax_kernel(float* __restrict__ S, const float* __restrict__ mask)
{
    const int row = blockIdx.x;
    const int b   = row >> 12;
    float* srow = S + (long long)row * SEQ;
    const float* mrow = mask + (long long)b * SEQ;
    const int t = threadIdx.x;

    float v[16];
    float mx = -INFINITY;
#pragma unroll
    for (int i = 0; i < 16; ++i) {
        int c = t + i * 256;
        v[i] = srow[c] + mrow[c];
        mx = fmaxf(mx, v[i]);
    }

    __shared__ float red[256];
    red[t] = mx; __syncthreads();
#pragma unroll
    for (int s = 128; s > 0; s >>= 1) {
        if (t < s) red[t] = fmaxf(red[t], red[t + s]);
        __syncthreads();
    }
    mx = red[0];
    __syncthreads();

    float sum = 0.f;
#pragma unroll
    for (int i = 0; i < 16; ++i) {
        v[i] = __expf(v[i] - mx);
        sum += v[i];
    }
    red[t] = sum; __syncthreads();
#pragma unroll
    for (int s = 128; s > 0; s >>= 1) {
        if (t < s) red[t] += red[t + s];
        __syncthreads();
    }
    const float inv = 1.f / red[0];

#pragma unroll
    for (int i = 0; i < 16; ++i)
        srow[t + i * 256] = f2tf32(v[i] * inv);
}

// ---------------- launch -----------------------------------------------------
extern "C" void kernel_launch(void* const* d_in, const int* in_sizes, int n_in,
                              void* d_out, int out_size)
{
    const float* hs   = (const float*)d_in[0];  // [B,S,H]
    const float* mask = (const float*)d_in[1];  // [B,1,S]
    const float* Wq   = (const float*)d_in[2];  // [H,H]
    const float* bq   = (const float*)d_in[3];
    const float* Wk   = (const float*)d_in[4];
    const float* bk   = (const float*)d_in[5];
    const float* Wv   = (const float*)d_in[6];
    const float* bv   = (const float*)d_in[7];
    float* out = (float*)d_out;

    float *p_q, *p_k, *p_vt, *p_s;
    cudaGetSymbolAddress((void**)&p_q,  g_q);
    cudaGetSymbolAddress((void**)&p_k,  g_k);
    cudaGetSymbolAddress((void**)&p_vt, g_vt);
    cudaGetSymbolAddress((void**)&p_s,  g_s);

    cudaFuncSetAttribute(gemm_tf32,
                         cudaFuncAttributeMaxDynamicSharedMemorySize, SMEM_TF32);

    const int MS = BATCH * SEQ;   // 8192
    dim3 blk(256);

    // Q/K/V projections (fp32 path, tf32-rounded outputs; V stored transposed)
    dim3 gqkv(HID / BN, MS / BM, 1);
    gemm_f32_qkv<false><<<gqkv, blk>>>(hs, Wq, bq, p_q,  MS, HID, HID);
    gemm_f32_qkv<false><<<gqkv, blk>>>(hs, Wk, bk, p_k,  MS, HID, HID);
    gemm_f32_qkv<true ><<<gqkv, blk>>>(hs, Wv, bv, p_vt, MS, HID, HID);

    // scores[b] = (Q[b] @ K[b]^T) / sqrt(128)  (tf32 tensor cores, batched)
    dim3 gsc(SEQ / 128, SEQ / 128, BATCH);
    gemm_tf32<<<gsc, blk, SMEM_TF32>>>(
        p_q, p_k, p_s, SEQ, SEQ, HID, SOFTMAX_SCALE,
        (long long)SEQ * HID, (long long)SEQ * HID, (long long)SEQ * SEQ);

    // softmax(scores + mask), output tf32-rounded
    softmax_kernel<<<BATCH * SEQ, 256>>>(p_s, mask);

    // context[b] = P[b] @ Vt[b]^T  (tf32 tensor cores, batched)
    dim3 gct(HID / 128, SEQ / 128, BATCH);
    gemm_tf32<<<gct, blk, SMEM_TF32>>>(
        p_s, p_vt, out, SEQ, HID, SEQ, 1.f,
        (long long)SEQ * SEQ, (long long)HID * SEQ, (long long)SEQ * HID);
}

// round 8
// speedup vs baseline: 4.2061x; 2.3927x over previous
#include <cuda_runtime.h>
#include <cuda_bf16.h>
#include <math.h>
#include <stdint.h>

// Problem shapes (fixed by the dataset)
#define BATCH 2
#define SEQ   4096
#define HID   2048
#define SOFTMAX_SCALE 0.08838834764831843f  /* 1/sqrt(128) */

#define SMEM_TF32 65536  /* tf32 gemm: 2 stages * (A 16KB + B 16KB) */
#define SMEM_BF16 65536  /* bf16 gemm: 2 stages * 4 tiles * 8KB */

// ---------------- scratch (__device__ globals: allocation-free rule) ---------
__device__ float g_q [(long long)BATCH * SEQ * HID];   // tf32(Q)
__device__ float g_k [(long long)BATCH * SEQ * HID];   // tf32(K)
__device__ float g_vt[(long long)BATCH * HID * SEQ];   // tf32(V^T) [b][h][s]
__device__ float g_s [(long long)BATCH * SEQ * SEQ];   // scores / probs
__device__ __nv_bfloat16 g_xhi[(long long)BATCH * SEQ * HID];
__device__ __nv_bfloat16 g_xlo[(long long)BATCH * SEQ * HID];
__device__ __nv_bfloat16 g_whi[(long long)3 * HID * HID];
__device__ __nv_bfloat16 g_wlo[(long long)3 * HID * HID];

// ---------------- PTX helpers ------------------------------------------------
__device__ __forceinline__ float f2tf32(float x) {
    uint32_t u;
    asm("cvt.rna.tf32.f32 %0, %1;" : "=r"(u) : "f"(x));
    return __uint_as_float(u);
}

__device__ __forceinline__ void ldsm4(uint32_t* r, uint32_t addr) {
    asm volatile("ldmatrix.sync.aligned.m8n8.x4.shared.b16 {%0,%1,%2,%3}, [%4];\n"
                 : "=r"(r[0]), "=r"(r[1]), "=r"(r[2]), "=r"(r[3]) : "r"(addr));
}

__device__ __forceinline__ void mma_tf32(float* d, const uint32_t* a, const uint32_t* b) {
    asm volatile(
        "mma.sync.aligned.m16n8k8.row.col.f32.tf32.tf32.f32 "
        "{%0,%1,%2,%3}, {%4,%5,%6,%7}, {%8,%9}, {%0,%1,%2,%3};\n"
        : "+f"(d[0]), "+f"(d[1]), "+f"(d[2]), "+f"(d[3])
        : "r"(a[0]), "r"(a[1]), "r"(a[2]), "r"(a[3]), "r"(b[0]), "r"(b[1]));
}

__device__ __forceinline__ void mma_bf16(float* d, const uint32_t* a, const uint32_t* b) {
    asm volatile(
        "mma.sync.aligned.m16n8k16.row.col.f32.bf16.bf16.f32 "
        "{%0,%1,%2,%3}, {%4,%5,%6,%7}, {%8,%9}, {%0,%1,%2,%3};\n"
        : "+f"(d[0]), "+f"(d[1]), "+f"(d[2]), "+f"(d[3])
        : "r"(a[0]), "r"(a[1]), "r"(a[2]), "r"(a[3]), "r"(b[0]), "r"(b[1]));
}

__device__ __forceinline__ void cp_async16(uint32_t dst, const void* src) {
    asm volatile("cp.async.cg.shared.global [%0], [%1], 16;\n" :: "r"(dst), "l"(src));
}
__device__ __forceinline__ void cp_commit() { asm volatile("cp.async.commit_group;\n"); }
__device__ __forceinline__ void cp_wait1()  { asm volatile("cp.async.wait_group 1;\n"); }
__device__ __forceinline__ void cp_wait0()  { asm volatile("cp.async.wait_group 0;\n"); }

// ============================================================================
// split fp32 -> (hi, lo) bf16 pair:  x ~= hi + lo
// ============================================================================
__global__ __launch_bounds__(256)
void split_bf16_kernel(const float* __restrict__ in,
                       __nv_bfloat16* __restrict__ hi,
                       __nv_bfloat16* __restrict__ lo, long long n8)
{
    long long i = (long long)blockIdx.x * blockDim.x + threadIdx.x;
    const long long stride = (long long)gridDim.x * blockDim.x;
    for (; i < n8; i += stride) {
        float4 v0 = reinterpret_cast<const float4*>(in)[2 * i];
        float4 v1 = reinterpret_cast<const float4*>(in)[2 * i + 1];
        float f[8] = {v0.x, v0.y, v0.z, v0.w, v1.x, v1.y, v1.z, v1.w};
        unsigned short hb[8], lb[8];
#pragma unroll
        for (int j = 0; j < 8; ++j) {
            __nv_bfloat16 h = __float2bfloat16(f[j]);
            __nv_bfloat16 l = __float2bfloat16(f[j] - __bfloat162float(h));
            hb[j] = __bfloat16_as_ushort(h);
            lb[j] = __bfloat16_as_ushort(l);
        }
        uint4 ho, loo;
        ho.x  = (uint32_t)hb[0] | ((uint32_t)hb[1] << 16);
        ho.y  = (uint32_t)hb[2] | ((uint32_t)hb[3] << 16);
        ho.z  = (uint32_t)hb[4] | ((uint32_t)hb[5] << 16);
        ho.w  = (uint32_t)hb[6] | ((uint32_t)hb[7] << 16);
        loo.x = (uint32_t)lb[0] | ((uint32_t)lb[1] << 16);
        loo.y = (uint32_t)lb[2] | ((uint32_t)lb[3] << 16);
        loo.z = (uint32_t)lb[4] | ((uint32_t)lb[5] << 16);
        loo.w = (uint32_t)lb[6] | ((uint32_t)lb[7] << 16);
        reinterpret_cast<uint4*>(hi)[i] = ho;
        reinterpret_cast<uint4*>(lo)[i] = loo;
    }
}

// ============================================================================
// bf16 split-3 NT GEMM (tensor core) for the QKV projections.
// C = (Ahi+Alo)[M,K] @ (Bhi+Blo)[N,K]^T + bias (dropping the lo*lo term).
// Output tf32-rounded f32; V variant stores transposed [h][s].
// BM=BN=128, BK=32, 8 warps (4x2), warp tile 32x64, mma m16n8k16.
// smem tile: [128 rows][32 bf16] = 64B/row, pair-row XOR swizzle.
// ============================================================================
template<bool STORE_TRANS>
__global__ __launch_bounds__(256, 2)
void gemm_bf16_qkv(const __nv_bfloat16* __restrict__ Ahi,
                   const __nv_bfloat16* __restrict__ Alo,
                   const __nv_bfloat16* __restrict__ Bhi,
                   const __nv_bfloat16* __restrict__ Blo,
                   const float* __restrict__ bias, float* __restrict__ C,
                   int M, int N, int K)
{
    extern __shared__ char smc[];
    const int tid    = threadIdx.x;
    const int lane   = tid & 31;
    const int wid    = tid >> 5;
    const int warp_m = wid & 3;
    const int warp_n = wid >> 2;
    const long long row0 = (long long)blockIdx.y * 128;
    const long long col0 = (long long)blockIdx.x * 128;

    const uint32_t smem_base = (uint32_t)__cvta_generic_to_shared(smc);

    float acc[2][8][4];
#pragma unroll
    for (int t = 0; t < 2; ++t)
#pragma unroll
        for (int j = 0; j < 8; ++j)
#pragma unroll
            for (int r = 0; r < 4; ++r) acc[t][j][r] = 0.f;

    const int KT = K >> 5;  // BK = 32

    // byte offset of 16B chunk (r, c) inside an 8KB [128][32bf16] tile
    auto toff = [](int r, int c) -> uint32_t {
        return (uint32_t)(((r >> 1) << 7) + (((((r & 1) << 2) + c) ^ ((r >> 1) & 7)) << 4));
    };

    auto stage = [&](int kt, int buf) {
        const long long k0 = (long long)kt * 32;
        const uint32_t base = smem_base + buf * 32768u;
#pragma unroll
        for (int p = 0; p < 2; ++p) {
            int idx = p * 256 + tid;     // 0..511
            int r = idx >> 2;            // row 0..127
            int c = idx & 3;             // 16B chunk 0..3
            uint32_t off = toff(r, c);
            const long long ga = (row0 + r) * K + k0 + c * 8;
            const long long gb = (col0 + r) * K + k0 + c * 8;
            cp_async16(base + off,          Ahi + ga);
            cp_async16(base + 8192u + off,  Alo + ga);
            cp_async16(base + 16384u + off, Bhi + gb);
            cp_async16(base + 24576u + off, Blo + gb);
        }
    };

    const int r15  = lane & 15;
    const int a_h  = lane >> 4;                        // A chunk half
    const int brow = (lane & 7) + ((lane >> 4) << 3);  // B row 0..15
    const int b_h  = (lane >> 3) & 1;                  // B chunk half

    auto compute = [&](int buf) {
        const uint32_t base = smem_base + buf * 32768u;
#pragma unroll
        for (int ks = 0; ks < 2; ++ks) {   // two k16 steps per BK=32
            uint32_t ahi[2][4], alo[2][4];
#pragma unroll
            for (int t = 0; t < 2; ++t) {
                int row = warp_m * 32 + t * 16 + r15;
                int ch  = ks * 2 + a_h;
                uint32_t off = toff(row, ch);
                ldsm4(ahi[t], base + off);
                ldsm4(alo[t], base + 8192u + off);
            }
#pragma unroll
            for (int u = 0; u < 4; ++u) {
                int row = warp_n * 64 + u * 16 + brow;
                int ch  = ks * 2 + b_h;
                uint32_t off = toff(row, ch);
                uint32_t bh[4], bl[4];
                ldsm4(bh, base + 16384u + off);
                ldsm4(bl, base + 24576u + off);
#pragma unroll
                for (int t = 0; t < 2; ++t) {
                    mma_bf16(acc[t][2*u  ], ahi[t], bh);
                    mma_bf16(acc[t][2*u  ], ahi[t], bl);
                    mma_bf16(acc[t][2*u  ], alo[t], bh);
                    mma_bf16(acc[t][2*u+1], ahi[t], bh + 2);
                    mma_bf16(acc[t][2*u+1], ahi[t], bl + 2);
                    mma_bf16(acc[t][2*u+1], alo[t], bh + 2);
                }
            }
        }
    };

    stage(0, 0); cp_commit();
    for (int kt = 0; kt < KT; ++kt) {
        if (kt + 1 < KT) { stage(kt + 1, (kt + 1) & 1); cp_commit(); cp_wait1(); }
        else            { cp_wait0(); }
        __syncthreads();
        compute(kt & 1);
        __syncthreads();
    }

    // ---------------- epilogue: + bias, tf32-round, (optional) transpose ----
    const int lrow = lane >> 2;
    const int lcol = (lane & 3) * 2;
#pragma unroll
    for (int t = 0; t < 2; ++t)
#pragma unroll
        for (int j = 0; j < 8; ++j) {
            const long long gcol = col0 + warp_n * 64 + j * 8 + lcol;
            const float b0v = bias[gcol];
            const float b1v = bias[gcol + 1];
#pragma unroll
            for (int h = 0; h < 2; ++h) {
                const long long grow = row0 + warp_m * 32 + t * 16 + lrow + h * 8;
                float v0 = f2tf32(acc[t][j][h * 2 + 0] + b0v);
                float v1 = f2tf32(acc[t][j][h * 2 + 1] + b1v);
                if (STORE_TRANS) {
                    // out[b][h][s]: b = grow/SEQ, s = grow%SEQ
                    const long long bb = grow >> 12;
                    const long long s  = grow & 4095;
                    float* Ct = C + bb * ((long long)HID * SEQ);
                    Ct[gcol * SEQ + s]       = v0;
                    Ct[(gcol + 1) * SEQ + s] = v1;
                } else {
                    *reinterpret_cast<float2*>(&C[grow * N + gcol]) = make_float2(v0, v1);
                }
            }
        }
}

// ============================================================================
// tf32 NT GEMM (tensor core) for scores and context — unchanged, R7-proven.
// ============================================================================
__global__ __launch_bounds__(256)
void gemm_tf32(const float* __restrict__ A, const float* __restrict__ B,
               float* __restrict__ C, int M, int N, int K, float alpha,
               long long sA, long long sB, long long sC)
{
    extern __shared__ float sm[];
    const int tid    = threadIdx.x;
    const int lane   = tid & 31;
    const int wid    = tid >> 5;
    const int warp_m = wid & 3;
    const int warp_n = wid >> 2;
    const long long row0 = (long long)blockIdx.y * 128;
    const long long col0 = (long long)blockIdx.x * 128;

    const float* Ab = A + (long long)blockIdx.z * sA;
    const float* Bb = B + (long long)blockIdx.z * sB;

    const uint32_t smem_base = (uint32_t)__cvta_generic_to_shared(sm);

    float acc[2][8][4];
#pragma unroll
    for (int t = 0; t < 2; ++t)
#pragma unroll
        for (int j = 0; j < 8; ++j)
#pragma unroll
            for (int r = 0; r < 4; ++r) acc[t][j][r] = 0.f;

    const int KT = K >> 5;

    auto stage = [&](int kt, int buf) {
        const long long k0 = (long long)kt * 32;
        const uint32_t abase = smem_base + buf * 32768u;
        const uint32_t bbase = abase + 16384u;
#pragma unroll
        for (int p = 0; p < 4; ++p) {
            int idx = p * 256 + tid;
            int m = idx >> 3;
            int c = idx & 7;
            uint32_t off = (uint32_t)(((m << 3) + (c ^ (m & 7))) << 4);
            cp_async16(abase + off, Ab + (row0 + m) * K + k0 + c * 4);
            cp_async16(bbase + off, Bb + (col0 + m) * K + k0 + c * 4);
        }
    };

    const int r15       = lane & 15;
    const int a_chunk_h = lane >> 4;
    const int b_row_off = (lane & 7) + ((lane >> 4) << 3);
    const int b_chunk_h = (lane >> 3) & 1;

    auto compute = [&](int buf) {
        const uint32_t abase = smem_base + buf * 32768u;
        const uint32_t bbase = abase + 16384u;
#pragma unroll
        for (int ks = 0; ks < 4; ++ks) {
            uint32_t a[2][4];
#pragma unroll
            for (int t = 0; t < 2; ++t) {
                int row   = warp_m * 32 + t * 16 + r15;
                int chunk = 2 * ks + a_chunk_h;
                ldsm4(a[t], abase + (uint32_t)(((row << 3) + (chunk ^ (row & 7))) << 4));
            }
            uint32_t b[8][2];
#pragma unroll
            for (int u = 0; u < 4; ++u) {
                int row   = warp_n * 64 + u * 16 + b_row_off;
                int chunk = 2 * ks + b_chunk_h;
                uint32_t r[4];
                ldsm4(r, bbase + (uint32_t)(((row << 3) + (chunk ^ (row & 7))) << 4));
                b[2*u  ][0] = r[0]; b[2*u  ][1] = r[1];
                b[2*u+1][0] = r[2]; b[2*u+1][1] = r[3];
            }
#pragma unroll
            for (int t = 0; t < 2; ++t)
#pragma unroll
                for (int j = 0; j < 8; ++j)
                    mma_tf32(acc[t][j], a[t], b[j]);
        }
    };

    stage(0, 0); cp_commit();
    for (int kt = 0; kt < KT; ++kt) {
        if (kt + 1 < KT) { stage(kt + 1, (kt + 1) & 1); cp_commit(); cp_wait1(); }
        else            { cp_wait0(); }
        __syncthreads();
        compute(kt & 1);
        __syncthreads();
    }

    float* Cb = C + (long long)blockIdx.z * sC;
    const int lrow = lane >> 2;
    const int lcol = (lane & 3) * 2;
#pragma unroll
    for (int t = 0; t < 2; ++t)
#pragma unroll
        for (int j = 0; j < 8; ++j) {
            const long long gcol = col0 + warp_n * 64 + j * 8 + lcol;
#pragma unroll
            for (int h = 0; h < 2; ++h) {
                const long long grow = row0 + warp_m * 32 + t * 16 + lrow + h * 8;
                float v0 = acc[t][j][h * 2 + 0] * alpha;
                float v1 = acc[t][j][h * 2 + 1] * alpha;
                *reinterpret_cast<float2*>(&Cb[grow * N + gcol]) = make_float2(v0, v1);
            }
        }
}

// ---------------- softmax (in place) + tf32-round output ---------------------
__global__ __launch_bounds__(256)
void softmax_kernel(float* __restrict__ S, const float* __restrict__ mask)
{
    const int row = blockIdx.x;
    const int b   = row >> 12;
    float* srow = S + (long long)row * SEQ;
    const float* mrow = mask + (long long)b * SEQ;
    const int t = threadIdx.x;

    float v[16];
    float mx = -INFINITY;
#pragma unroll
    for (int i = 0; i < 16; ++i) {
        int c = t + i * 256;
        v[i] = srow[c] + mrow[c];
        mx = fmaxf(mx, v[i]);
    }

    __shared__ float red[256];
    red[t] = mx; __syncthreads();
#pragma unroll
    for (int s = 128; s > 0; s >>= 1) {
        if (t < s) red[t] = fmaxf(red[t], red[t + s]);
        __syncthreads();
    }
    mx = red[0];
    __syncthreads();

    float sum = 0.f;
#pragma unroll
    for (int i = 0; i < 16; ++i) {
        v[i] = __expf(v[i] - mx);
        sum += v[i];
    }
    red[t] = sum; __syncthreads();
#pragma unroll
    for (int s = 128; s > 0; s >>= 1) {
        if (t < s) red[t] += red[t + s];
        __syncthreads();
    }
    const float inv = 1.f / red[0];

#pragma unroll
    for (int i = 0; i < 16; ++i)
        srow[t + i * 256] = f2tf32(v[i] * inv);
}

// ---------------- launch -----------------------------------------------------
extern "C" void kernel_launch(void* const* d_in, const int* in_sizes, int n_in,
                              void* d_out, int out_size)
{
    const float* hs   = (const float*)d_in[0];  // [B,S,H]
    const float* mask = (const float*)d_in[1];  // [B,1,S]
    const float* Wq   = (const float*)d_in[2];  // [H,H]
    const float* bq   = (const float*)d_in[3];
    const float* Wk   = (const float*)d_in[4];
    const float* bk   = (const float*)d_in[5];
    const float* Wv   = (const float*)d_in[6];
    const float* bv   = (const float*)d_in[7];
    float* out = (float*)d_out;

    float *p_q, *p_k, *p_vt, *p_s;
    __nv_bfloat16 *p_xhi, *p_xlo, *p_whi, *p_wlo;
    cudaGetSymbolAddress((void**)&p_q,   g_q);
    cudaGetSymbolAddress((void**)&p_k,   g_k);
    cudaGetSymbolAddress((void**)&p_vt,  g_vt);
    cudaGetSymbolAddress((void**)&p_s,   g_s);
    cudaGetSymbolAddress((void**)&p_xhi, g_xhi);
    cudaGetSymbolAddress((void**)&p_xlo, g_xlo);
    cudaGetSymbolAddress((void**)&p_whi, g_whi);
    cudaGetSymbolAddress((void**)&p_wlo, g_wlo);

    cudaFuncSetAttribute(gemm_tf32,
                         cudaFuncAttributeMaxDynamicSharedMemorySize, SMEM_TF32);
    cudaFuncSetAttribute(gemm_bf16_qkv<false>,
                         cudaFuncAttributeMaxDynamicSharedMemorySize, SMEM_BF16);
    cudaFuncSetAttribute(gemm_bf16_qkv<true>,
                         cudaFuncAttributeMaxDynamicSharedMemorySize, SMEM_BF16);

    const long long HH = (long long)HID * HID;
    const int MS = BATCH * SEQ;   // 8192
    dim3 blk(256);

    // split fp32 -> bf16 (hi, lo)
    split_bf16_kernel<<<2048, 256>>>(hs, p_xhi, p_xlo, (long long)MS * HID / 8);
    split_bf16_kernel<<<1024, 256>>>(Wq, p_whi,          p_wlo,          HH / 8);
    split_bf16_kernel<<<1024, 256>>>(Wk, p_whi + HH,     p_wlo + HH,     HH / 8);
    split_bf16_kernel<<<1024, 256>>>(Wv, p_whi + 2 * HH, p_wlo + 2 * HH, HH / 8);

    // Q/K/V projections (bf16 split-3 tensor cores; V stored transposed)
    dim3 gqkv(HID / 128, MS / 128, 1);
    gemm_bf16_qkv<false><<<gqkv, blk, SMEM_BF16>>>(
        p_xhi, p_xlo, p_whi,          p_wlo,          bq, p_q,  MS, HID, HID);
    gemm_bf16_qkv<false><<<gqkv, blk, SMEM_BF16>>>(
        p_xhi, p_xlo, p_whi + HH,     p_wlo + HH,     bk, p_k,  MS, HID, HID);
    gemm_bf16_qkv<true ><<<gqkv, blk, SMEM_BF16>>>(
        p_xhi, p_xlo, p_whi + 2 * HH, p_wlo + 2 * HH, bv, p_vt, MS, HID, HID);

    // scores[b] = (Q[b] @ K[b]^T) / sqrt(128)  (tf32 tensor cores, batched)
    dim3 gsc(SEQ / 128, SEQ / 128, BATCH);
    gemm_tf32<<<gsc, blk, SMEM_TF32>>>(
        p_q, p_k, p_s, SEQ, SEQ, HID, SOFTMAX_SCALE,
        (long long)SEQ * HID, (long long)SEQ * HID, (long long)SEQ * SEQ);

    // softmax(scores + mask), output tf32-rounded
    softmax_kernel<<<BATCH * SEQ, 256>>>(p_s, mask);

    // context[b] = P[b] @ Vt[b]^T  (tf32 tensor cores, batched)
    dim3 gct(HID / 128, SEQ / 128, BATCH);
    gemm_tf32<<<gct, blk, SMEM_TF32>>>(
        p_s, p_vt, out, SEQ, HID, SEQ, 1.f,
        (long long)SEQ * SEQ, (long long)HID * SEQ, (long long)SEQ * HID);
}